// round 1
// baseline (speedup 1.0000x reference)
#include <cuda_runtime.h>
#include <cstdint>

// ---------------- problem constants ----------------
#define NB 4
#define NC 512
#define NG 2048
#define CH 3
#define NP 3
#define OC 64
#define NBAS 10
#define EPSV 1e-6f
#define BN_EPS 1e-5f

// output layout (float32, concatenated in return order)
#define OFF_Y   0                         // (4,2048,64)  = 524288
#define OFF_NF  524288                    // (4,2048,9)   = 73728
#define OFF_FP  598016                    // (4,2048,3,3) = 73728
#define OFF_NH1 671744                    // (4,2048,3,3) = 73728
#define OFF_H0  745472                    // (4,2048,9)   = 73728

// scratch (device globals; no allocation allowed)
__device__ float g_pos[NB * NG * 9];     // n_h1_pos (conv input)
__device__ float g_conv[NB * NG * 9];    // conv output (pre-BN)
__device__ float g_stats[18];            // mean[9], inv_std[9]

__device__ __forceinline__ float ex2f(float x) {
    float y;
    asm("ex2.approx.ftz.f32 %0, %1;" : "=f"(y) : "f"(x));
    return y;
}

// ============================================================
// Kernel 1: RBF pairwise sums (h0, h1), n_h1, Fourier prior,
//           and n_h1_pos scratch. Warp per (b, g) point.
// ============================================================
__global__ void __launch_bounds__(256)
k1_rbf(const float* __restrict__ xc, const float* __restrict__ yc,
       const float* __restrict__ xg, const float* __restrict__ sigma,
       const float* __restrict__ mu, const float* __restrict__ eps1,
       const float* __restrict__ bu, const float* __restrict__ rw,
       float* __restrict__ out)
{
    __shared__ float sdat[NC * 8];            // swizzled {x0..2, y0..2} per n
    __shared__ float ssw[NBAS * NP];          // sample_w for this b
    __shared__ float ssb[NBAS * NP];          // sample_b
    __shared__ float srw[NBAS];
    __shared__ float scoef[NP];               // -0.5*inv^2*log2(e)

    const int b = blockIdx.y;
    const int tid = threadIdx.x;

    // stage context set into SMEM (bank-swizzled so LDS.128 is conflict-free)
    for (int idx = tid; idx < NC * CH; idx += 256) {
        int n = idx / 3, c = idx - n * 3;
        int sw = n & 4;                        // swizzle bit
        sdat[n * 8 + sw + c]        = xc[(b * NC + n) * 3 + c];
        sdat[n * 8 + (sw ^ 4) + c]  = yc[(b * NC + n) * 3 + c];
    }
    if (tid < NBAS * NP) {
        int k = tid / 3, p = tid - k * 3;
        float w_std = 1.0f / (expf(sigma[p]) + EPSV);
        ssw[tid] = expf(mu[p]) + w_std * eps1[(b * NBAS + k) * NP + p];
        ssb[tid] = 6.283185307179586f * bu[(b * NBAS + k) * NP + p];
    }
    if (tid >= 32 && tid < 32 + NBAS) srw[tid - 32] = rw[tid - 32];
    if (tid >= 64 && tid < 64 + NP) {
        int p = tid - 64;
        float inv = 1.0f / (expf(sigma[p]) + EPSV);
        scoef[p] = -0.5f * inv * inv * 1.4426950408889634f;   // fold log2(e) for ex2
    }
    __syncthreads();

    const int wid = tid >> 5, lane = tid & 31;
    const int g = blockIdx.x * 8 + wid;
    const float* xgp = &xg[(b * NG + g) * 3];
    const float xg0 = xgp[0], xg1 = xgp[1], xg2 = xgp[2];
    const float c0 = scoef[0], c1 = scoef[1], c2 = scoef[2];

    float h0[9], h1[9];
#pragma unroll
    for (int j = 0; j < 9; j++) { h0[j] = 0.f; h1[j] = 0.f; }

#pragma unroll 4
    for (int it = 0; it < NC / 32; ++it) {
        int n = it * 32 + lane;
        int sw = n & 4;
        float4 v = *reinterpret_cast<const float4*>(&sdat[n * 8 + sw]);        // x0,x1,x2,-
        float4 u = *reinterpret_cast<const float4*>(&sdat[n * 8 + (sw ^ 4)]);  // y0,y1,y2,-
        float d0 = v.x - xg0, d1 = v.y - xg1, d2 = v.z - xg2;
        float s0 = d0 * d0, s1 = d1 * d1, s2 = d2 * d2;
        float e;
        e = ex2f(s0 * c0); h0[0] += e; h1[0] = fmaf(e, u.x, h1[0]);
        e = ex2f(s0 * c1); h0[1] += e; h1[1] = fmaf(e, u.x, h1[1]);
        e = ex2f(s0 * c2); h0[2] += e; h1[2] = fmaf(e, u.x, h1[2]);
        e = ex2f(s1 * c0); h0[3] += e; h1[3] = fmaf(e, u.y, h1[3]);
        e = ex2f(s1 * c1); h0[4] += e; h1[4] = fmaf(e, u.y, h1[4]);
        e = ex2f(s1 * c2); h0[5] += e; h1[5] = fmaf(e, u.y, h1[5]);
        e = ex2f(s2 * c0); h0[6] += e; h1[6] = fmaf(e, u.z, h1[6]);
        e = ex2f(s2 * c1); h0[7] += e; h1[7] = fmaf(e, u.z, h1[7]);
        e = ex2f(s2 * c2); h0[8] += e; h1[8] = fmaf(e, u.z, h1[8]);
    }

    // warp butterfly reduction: afterwards every lane holds all 18 totals
#pragma unroll
    for (int off = 16; off > 0; off >>= 1) {
#pragma unroll
        for (int j = 0; j < 9; j++) {
            h0[j] += __shfl_xor_sync(0xffffffffu, h0[j], off);
            h1[j] += __shfl_xor_sync(0xffffffffu, h1[j], off);
        }
    }

    if (lane < 9) {
        float h0v = 0.f, h1v = 0.f;
        switch (lane) {
            case 0: h0v = h0[0]; h1v = h1[0]; break;
            case 1: h0v = h0[1]; h1v = h1[1]; break;
            case 2: h0v = h0[2]; h1v = h1[2]; break;
            case 3: h0v = h0[3]; h1v = h1[3]; break;
            case 4: h0v = h0[4]; h1v = h1[4]; break;
            case 5: h0v = h0[5]; h1v = h1[5]; break;
            case 6: h0v = h0[6]; h1v = h1[6]; break;
            case 7: h0v = h0[7]; h1v = h1[7]; break;
            case 8: h0v = h0[8]; h1v = h1[8]; break;
        }
        int c = lane / 3;
        int p = lane - c * 3;
        float xgc = (c == 0) ? xg0 : ((c == 1) ? xg1 : xg2);
        float nh1 = h1v / (h0v + EPSV);

        // Fourier prior: sqrt(2/NBAS) * sum_k rw[k]*cos(w*xg + b)
        // IMPORTANT: arg must be mul-then-add (no FMA) to match reference fp32 arg.
        float fp = 0.f;
#pragma unroll
        for (int k = 0; k < NBAS; k++) {
            float arg = __fadd_rn(__fmul_rn(ssw[k * 3 + p], xgc), ssb[k * 3 + p]);
            fp += srw[k] * cosf(arg);
        }
        fp *= 0.4472135954999579f;   // sqrt(0.2)

        int base = (b * NG + g) * 9 + lane;   // chan = c*3+p == lane
        out[OFF_H0 + base] = h0v;
        out[OFF_NH1 + base] = nh1;
        out[OFF_FP + base] = fp;
        g_pos[base] = nh1 + fp;
    }
}

// ============================================================
// Kernel 2: depthwise 1-D convs (k=3/5/9, pad=1/2/4) along g
// ============================================================
__global__ void __launch_bounds__(256)
k2_conv(const float* __restrict__ w1, const float* __restrict__ b1,
        const float* __restrict__ w2, const float* __restrict__ b2,
        const float* __restrict__ w3, const float* __restrict__ b3)
{
    int t = blockIdx.x * 256 + threadIdx.x;
    if (t >= NB * NG * 9) return;
    int b = t / (NG * 9);
    int r = t - b * NG * 9;
    int g = r / 9;
    int chan = r - g * 9;
    int c = chan / 3;
    int p = chan - c * 3;

    int ksz = (p == 0) ? 3 : ((p == 1) ? 5 : 9);
    int pad = ksz >> 1;
    const float* w = (p == 0) ? w1 : ((p == 1) ? w2 : w3);
    const float* bb = (p == 0) ? b1 : ((p == 1) ? b2 : b3);

    float acc = bb[c];
    const float* src = &g_pos[b * NG * 9 + chan];
    for (int tt = 0; tt < ksz; tt++) {
        int gg = g + tt - pad;
        if (gg >= 0 && gg < NG)
            acc = fmaf(src[gg * 9], w[c * ksz + tt], acc);
    }
    g_conv[t] = acc;
}

// ============================================================
// Kernel 3: BN stats per channel (deterministic, fp64 accum)
// ============================================================
__global__ void __launch_bounds__(256)
k3_stats()
{
    __shared__ double ss[256], sq[256];
    const int chan = blockIdx.x;     // 0..8
    const int tid = threadIdx.x;
    double s = 0.0, q = 0.0;
    for (int i = tid; i < NB * NG; i += 256) {
        double v = (double)g_conv[i * 9 + chan];
        s += v; q += v * v;
    }
    ss[tid] = s; sq[tid] = q;
    __syncthreads();
    for (int off = 128; off > 0; off >>= 1) {
        if (tid < off) { ss[tid] += ss[tid + off]; sq[tid] += sq[tid + off]; }
        __syncthreads();
    }
    if (tid == 0) {
        double m = ss[0] / (double)(NB * NG);
        double var = sq[0] / (double)(NB * NG) - m * m;
        if (var < 0.0) var = 0.0;
        g_stats[chan] = (float)m;
        g_stats[9 + chan] = (float)(1.0 / sqrt(var + (double)BN_EPS));
    }
}

// ============================================================
// Kernel 4: BN apply -> n_f, then feat(18) @ g_w.T + g_b -> y.
//           Warp per (b,g) point; lanes cover 64 outputs (2 each).
// ============================================================
__global__ void __launch_bounds__(256)
k4_head(const float* __restrict__ gamma, const float* __restrict__ beta,
        const float* __restrict__ gw, const float* __restrict__ gb,
        float* __restrict__ out)
{
    __shared__ float sw[OC * 18];
    __shared__ float sb[OC];
    const int tid = threadIdx.x;
    for (int i = tid; i < OC * 18; i += 256) sw[i] = gw[i];
    if (tid < OC) sb[tid] = gb[tid];
    __syncthreads();

    const int wid = tid >> 5, lane = tid & 31;
    const int i = blockIdx.x * 8 + wid;      // flat (b*NG+g)

    float f[18];
    const float* h0f = &out[OFF_H0 + i * 9];
#pragma unroll
    for (int j = 0; j < 9; j++) f[j] = h0f[j];
#pragma unroll
    for (int j = 0; j < 9; j++) {
        int c = j / 3, p = j - c * 3;
        float x = g_conv[i * 9 + j];
        float nf = gamma[p * CH + c] * (x - g_stats[j]) * g_stats[9 + j] + beta[p * CH + c];
        f[9 + j] = nf;
        if (lane == j) out[OFF_NF + i * 9 + j] = nf;
    }

#pragma unroll
    for (int half = 0; half < 2; half++) {
        int o = lane + half * 32;
        float acc = sb[o];
        const float* wr = &sw[o * 18];
#pragma unroll
        for (int k = 0; k < 18; k++) acc = fmaf(f[k], wr[k], acc);
        out[OFF_Y + i * OC + o] = acc;
    }
}

// ============================================================
extern "C" void kernel_launch(void* const* d_in, const int* in_sizes, int n_in,
                              void* d_out, int out_size)
{
    const float* xc    = (const float*)d_in[0];
    const float* yc    = (const float*)d_in[1];
    const float* xg    = (const float*)d_in[2];
    const float* sigma = (const float*)d_in[3];
    const float* mu    = (const float*)d_in[4];
    const float* eps1  = (const float*)d_in[5];
    const float* bu    = (const float*)d_in[6];
    const float* rw    = (const float*)d_in[7];
    const float* w1    = (const float*)d_in[8];
    const float* b1    = (const float*)d_in[9];
    const float* w2    = (const float*)d_in[10];
    const float* b2    = (const float*)d_in[11];
    const float* w3    = (const float*)d_in[12];
    const float* b3    = (const float*)d_in[13];
    const float* gamma = (const float*)d_in[14];
    const float* beta  = (const float*)d_in[15];
    const float* gw    = (const float*)d_in[16];
    const float* gb    = (const float*)d_in[17];
    float* out = (float*)d_out;

    dim3 grid1(NG / 8, NB);
    k1_rbf<<<grid1, 256>>>(xc, yc, xg, sigma, mu, eps1, bu, rw, out);
    k2_conv<<<(NB * NG * 9 + 255) / 256, 256>>>(w1, b1, w2, b2, w3, b3);
    k3_stats<<<9, 256>>>();
    k4_head<<<NB * NG / 8, 256>>>(gamma, beta, gw, gb, out);
}

// round 2
// speedup vs baseline: 1.0010x; 1.0010x over previous
#include <cuda_runtime.h>
#include <cstdint>

// ---------------- problem constants ----------------
#define NB 4
#define NC 512
#define NG 2048
#define CH 3
#define NP 3
#define OC 64
#define NBAS 10
#define NPT (NB * NG)                      // 8192 flat points
#define EPSV 1e-6f
#define BN_EPS 1e-5f

// output layout (float32, concatenated in return order)
#define OFF_Y   0                         // (4,2048,64)  = 524288
#define OFF_NF  524288                    // (4,2048,9)   = 73728
#define OFF_FP  598016                    // (4,2048,3,3) = 73728
#define OFF_NH1 671744                    // (4,2048,3,3) = 73728
#define OFF_H0  745472                    // (4,2048,9)   = 73728

// scratch (device globals; no allocation allowed). SoA: [chan][b][g]
__device__ float g_pos[9 * NPT];          // n_h1_pos (conv input)
__device__ float g_conv[9 * NPT];         // conv output (pre-BN)
__device__ float g_stats[18];             // mean[9], inv_std[9]

__device__ __forceinline__ float ex2f(float x) {
    float y;
    asm("ex2.approx.ftz.f32 %0, %1;" : "=f"(y) : "f"(x));
    return y;
}

// ============================================================
// Kernel 1: RBF pairwise sums (h0, h1), n_h1, Fourier prior,
//           and n_h1_pos scratch. Warp per (b, g) point.
// ============================================================
__global__ void __launch_bounds__(256)
k1_rbf(const float* __restrict__ xc, const float* __restrict__ yc,
       const float* __restrict__ xg, const float* __restrict__ sigma,
       const float* __restrict__ mu, const float* __restrict__ eps1,
       const float* __restrict__ bu, const float* __restrict__ rw,
       float* __restrict__ out)
{
    __shared__ float sdat[NC * 8];            // swizzled {x0..2, y0..2} per n
    __shared__ float ssw[NBAS * NP];          // sample_w for this b
    __shared__ float ssb[NBAS * NP];          // sample_b
    __shared__ float srw[NBAS];
    __shared__ float scoef[NP];               // -0.5*inv^2*log2(e)

    const int b = blockIdx.y;
    const int tid = threadIdx.x;

    // stage context set into SMEM (bank-swizzled so LDS.128 is conflict-free)
    for (int idx = tid; idx < NC * CH; idx += 256) {
        int n = idx / 3, c = idx - n * 3;
        int sw = n & 4;                        // swizzle bit
        sdat[n * 8 + sw + c]        = xc[(b * NC + n) * 3 + c];
        sdat[n * 8 + (sw ^ 4) + c]  = yc[(b * NC + n) * 3 + c];
    }
    if (tid < NBAS * NP) {
        int k = tid / 3, p = tid - k * 3;
        float w_std = 1.0f / (expf(sigma[p]) + EPSV);
        ssw[tid] = expf(mu[p]) + w_std * eps1[(b * NBAS + k) * NP + p];
        ssb[tid] = 6.283185307179586f * bu[(b * NBAS + k) * NP + p];
    }
    if (tid >= 32 && tid < 32 + NBAS) srw[tid - 32] = rw[tid - 32];
    if (tid >= 64 && tid < 64 + NP) {
        int p = tid - 64;
        float inv = 1.0f / (expf(sigma[p]) + EPSV);
        scoef[p] = -0.5f * inv * inv * 1.4426950408889634f;   // fold log2(e) for ex2
    }
    __syncthreads();

    const int wid = tid >> 5, lane = tid & 31;
    const int g = blockIdx.x * 8 + wid;
    const float* xgp = &xg[(b * NG + g) * 3];
    const float xg0 = xgp[0], xg1 = xgp[1], xg2 = xgp[2];
    const float c0 = scoef[0], c1 = scoef[1], c2 = scoef[2];

    float h0[9], h1[9];
#pragma unroll
    for (int j = 0; j < 9; j++) { h0[j] = 0.f; h1[j] = 0.f; }

#pragma unroll 4
    for (int it = 0; it < NC / 32; ++it) {
        int n = it * 32 + lane;
        int sw = n & 4;
        float4 v = *reinterpret_cast<const float4*>(&sdat[n * 8 + sw]);        // x0,x1,x2,-
        float4 u = *reinterpret_cast<const float4*>(&sdat[n * 8 + (sw ^ 4)]);  // y0,y1,y2,-
        float d0 = v.x - xg0, d1 = v.y - xg1, d2 = v.z - xg2;
        float s0 = d0 * d0, s1 = d1 * d1, s2 = d2 * d2;
        float e;
        e = ex2f(s0 * c0); h0[0] += e; h1[0] = fmaf(e, u.x, h1[0]);
        e = ex2f(s0 * c1); h0[1] += e; h1[1] = fmaf(e, u.x, h1[1]);
        e = ex2f(s0 * c2); h0[2] += e; h1[2] = fmaf(e, u.x, h1[2]);
        e = ex2f(s1 * c0); h0[3] += e; h1[3] = fmaf(e, u.y, h1[3]);
        e = ex2f(s1 * c1); h0[4] += e; h1[4] = fmaf(e, u.y, h1[4]);
        e = ex2f(s1 * c2); h0[5] += e; h1[5] = fmaf(e, u.y, h1[5]);
        e = ex2f(s2 * c0); h0[6] += e; h1[6] = fmaf(e, u.z, h1[6]);
        e = ex2f(s2 * c1); h0[7] += e; h1[7] = fmaf(e, u.z, h1[7]);
        e = ex2f(s2 * c2); h0[8] += e; h1[8] = fmaf(e, u.z, h1[8]);
    }

    // warp butterfly reduction: afterwards every lane holds all 18 totals
#pragma unroll
    for (int off = 16; off > 0; off >>= 1) {
#pragma unroll
        for (int j = 0; j < 9; j++) {
            h0[j] += __shfl_xor_sync(0xffffffffu, h0[j], off);
            h1[j] += __shfl_xor_sync(0xffffffffu, h1[j], off);
        }
    }

    if (lane < 9) {
        float h0v = 0.f, h1v = 0.f;
        switch (lane) {
            case 0: h0v = h0[0]; h1v = h1[0]; break;
            case 1: h0v = h0[1]; h1v = h1[1]; break;
            case 2: h0v = h0[2]; h1v = h1[2]; break;
            case 3: h0v = h0[3]; h1v = h1[3]; break;
            case 4: h0v = h0[4]; h1v = h1[4]; break;
            case 5: h0v = h0[5]; h1v = h1[5]; break;
            case 6: h0v = h0[6]; h1v = h1[6]; break;
            case 7: h0v = h0[7]; h1v = h1[7]; break;
            case 8: h0v = h0[8]; h1v = h1[8]; break;
        }
        int c = lane / 3;
        int p = lane - c * 3;
        float xgc = (c == 0) ? xg0 : ((c == 1) ? xg1 : xg2);
        float nh1 = h1v / (h0v + EPSV);

        // Fourier prior: sqrt(2/NBAS) * sum_k rw[k]*cos(w*xg + b)
        // IMPORTANT: arg must be mul-then-add (no FMA) to match reference fp32 arg.
        float fp = 0.f;
#pragma unroll
        for (int k = 0; k < NBAS; k++) {
            float arg = __fadd_rn(__fmul_rn(ssw[k * 3 + p], xgc), ssb[k * 3 + p]);
            fp += srw[k] * cosf(arg);
        }
        fp *= 0.4472135954999579f;   // sqrt(0.2)

        int base = (b * NG + g) * 9 + lane;   // chan = c*3+p == lane
        out[OFF_H0 + base] = h0v;
        out[OFF_NH1 + base] = nh1;
        out[OFF_FP + base] = fp;
        // SoA scratch for conv/stats: [chan][b][g]
        g_pos[(lane * NB + b) * NG + g] = nh1 + fp;
    }
}

// ============================================================
// Kernel 2: depthwise 1-D convs (k=3/5/9, pad=1/2/4) along g
//           SoA layout -> fully coalesced loads/stores
// ============================================================
__global__ void __launch_bounds__(256)
k2_conv(const float* __restrict__ w1, const float* __restrict__ b1,
        const float* __restrict__ w2, const float* __restrict__ b2,
        const float* __restrict__ w3, const float* __restrict__ b3)
{
    int t = blockIdx.x * 256 + threadIdx.x;
    if (t >= 9 * NPT) return;
    int chan = t / NPT;            // 0..8, chan = c*3+p
    int rem  = t - chan * NPT;
    int g    = rem % NG;
    int c = chan / 3;
    int p = chan - c * 3;

    int ksz = (p == 0) ? 3 : ((p == 1) ? 5 : 9);
    int pad = ksz >> 1;
    const float* w  = (p == 0) ? w1 : ((p == 1) ? w2 : w3);
    const float* bb = (p == 0) ? b1 : ((p == 1) ? b2 : b3);

    float acc = bb[c];
    const float* src = &g_pos[t - g];      // row start: [chan][b][0]
    for (int tt = 0; tt < ksz; tt++) {
        int gg = g + tt - pad;
        if (gg >= 0 && gg < NG)
            acc = fmaf(src[gg], w[c * ksz + tt], acc);
    }
    g_conv[t] = acc;
}

// ============================================================
// Kernel 3: BN stats per channel (deterministic, fp64 accum,
//           coalesced SoA loads, 4-way ILP)
// ============================================================
__global__ void __launch_bounds__(256)
k3_stats()
{
    __shared__ double ss[256], sq[256];
    const int chan = blockIdx.x;     // 0..8
    const int tid = threadIdx.x;
    const float* src = &g_conv[chan * NPT];
    double s[4] = {0, 0, 0, 0}, q[4] = {0, 0, 0, 0};
#pragma unroll
    for (int k = 0; k < NPT / 256; k++) {
        double v = (double)src[tid + k * 256];
        s[k & 3] += v;
        q[k & 3] = fma(v, v, q[k & 3]);
    }
    ss[tid] = (s[0] + s[1]) + (s[2] + s[3]);
    sq[tid] = (q[0] + q[1]) + (q[2] + q[3]);
    __syncthreads();
    for (int off = 128; off > 0; off >>= 1) {
        if (tid < off) { ss[tid] += ss[tid + off]; sq[tid] += sq[tid + off]; }
        __syncthreads();
    }
    if (tid == 0) {
        double m = ss[0] / (double)NPT;
        double var = sq[0] / (double)NPT - m * m;
        if (var < 0.0) var = 0.0;
        g_stats[chan] = (float)m;
        g_stats[9 + chan] = (float)(1.0 / sqrt(var + (double)BN_EPS));
    }
}

// ============================================================
// Kernel 4: BN apply -> n_f, then feat(18) @ g_w.T + g_b -> y.
//           Block = 256 threads handles 32 points; all operands
//           staged in SMEM; 8 threads/point x 8 outputs each.
// ============================================================
__global__ void __launch_bounds__(256)
k4_head(const float* __restrict__ gamma, const float* __restrict__ beta,
        const float* __restrict__ gw, const float* __restrict__ gb,
        float* __restrict__ out)
{
    __shared__ float sfeat[32 * 19];     // [point][18 feats], padded row 19
    __shared__ float swT[18 * 64];       // transposed weights [k][o]
    __shared__ float sb[OC];
    __shared__ float sstat[18];
    __shared__ float sgam[9], sbet[9];

    const int tid = threadIdx.x;
    const int base = blockIdx.x * 32;    // flat point index (b*NG+g)

    // stage weights (transposed), bias, stats, BN params
    for (int idx = tid; idx < OC * 18; idx += 256) {
        int o = idx / 18, k = idx - o * 18;
        swT[k * 64 + o] = gw[idx];
    }
    if (tid < OC) sb[tid] = gb[tid];
    if (tid >= 64 && tid < 82) sstat[tid - 64] = g_stats[tid - 64];
    if (tid >= 96 && tid < 105) {
        int j = tid - 96;                 // chan j = c*3+p
        int c = j / 3, p = j - c * 3;
        sgam[j] = gamma[p * CH + c];
        sbet[j] = beta[p * CH + c];
    }
    __syncthreads();                      // sstat/sgam ready before BN below

    // stage h0 feats (coalesced from out) and conv+BN feats (coalesced SoA)
    for (int idx = tid; idx < 288; idx += 256)
        sfeat[(idx / 9) * 19 + (idx % 9)] = out[OFF_H0 + base * 9 + idx];
    for (int idx = tid; idx < 288; idx += 256) {
        int j = idx >> 5, t = idx & 31;   // channel, point-in-block
        float x = g_conv[j * NPT + base + t];
        float nf = sgam[j] * (x - sstat[j]) * sstat[9 + j] + sbet[j];
        sfeat[t * 19 + 9 + j] = nf;
    }
    __syncthreads();

    // write n_f (coalesced from SMEM)
    for (int idx = tid; idx < 288; idx += 256)
        out[OFF_NF + base * 9 + idx] = sfeat[(idx / 9) * 19 + 9 + (idx % 9)];

    // matvec: 8 threads per point, 8 outputs each
    const int pt = tid >> 3;              // 0..31
    const int og = (tid & 7) * 8;         // output group start
    const float* f = &sfeat[pt * 19];
    float acc[8];
#pragma unroll
    for (int oi = 0; oi < 8; oi++) acc[oi] = sb[og + oi];
#pragma unroll
    for (int k = 0; k < 18; k++) {
        float fv = f[k];
        float4 wa = *reinterpret_cast<const float4*>(&swT[k * 64 + og]);
        float4 wb = *reinterpret_cast<const float4*>(&swT[k * 64 + og + 4]);
        acc[0] = fmaf(fv, wa.x, acc[0]);
        acc[1] = fmaf(fv, wa.y, acc[1]);
        acc[2] = fmaf(fv, wa.z, acc[2]);
        acc[3] = fmaf(fv, wa.w, acc[3]);
        acc[4] = fmaf(fv, wb.x, acc[4]);
        acc[5] = fmaf(fv, wb.y, acc[5]);
        acc[6] = fmaf(fv, wb.z, acc[6]);
        acc[7] = fmaf(fv, wb.w, acc[7]);
    }
    float* yo = &out[OFF_Y + (base + pt) * OC + og];
    *reinterpret_cast<float4*>(yo)     = make_float4(acc[0], acc[1], acc[2], acc[3]);
    *reinterpret_cast<float4*>(yo + 4) = make_float4(acc[4], acc[5], acc[6], acc[7]);
}

// ============================================================
extern "C" void kernel_launch(void* const* d_in, const int* in_sizes, int n_in,
                              void* d_out, int out_size)
{
    const float* xc    = (const float*)d_in[0];
    const float* yc    = (const float*)d_in[1];
    const float* xg    = (const float*)d_in[2];
    const float* sigma = (const float*)d_in[3];
    const float* mu    = (const float*)d_in[4];
    const float* eps1  = (const float*)d_in[5];
    const float* bu    = (const float*)d_in[6];
    const float* rw    = (const float*)d_in[7];
    const float* w1    = (const float*)d_in[8];
    const float* b1    = (const float*)d_in[9];
    const float* w2    = (const float*)d_in[10];
    const float* b2    = (const float*)d_in[11];
    const float* w3    = (const float*)d_in[12];
    const float* b3    = (const float*)d_in[13];
    const float* gamma = (const float*)d_in[14];
    const float* beta  = (const float*)d_in[15];
    const float* gw    = (const float*)d_in[16];
    const float* gb    = (const float*)d_in[17];
    float* out = (float*)d_out;

    dim3 grid1(NG / 8, NB);
    k1_rbf<<<grid1, 256>>>(xc, yc, xg, sigma, mu, eps1, bu, rw, out);
    k2_conv<<<(9 * NPT + 255) / 256, 256>>>(w1, b1, w2, b2, w3, b3);
    k3_stats<<<9, 256>>>();
    k4_head<<<NPT / 32, 256>>>(gamma, beta, gw, gb, out);
}